// round 11
// baseline (speedup 1.0000x reference)
#include <cuda_runtime.h>
#include <cuda_bf16.h>
#include <math.h>
#include <stdint.h>

// Problem constants
#define BB 32
#define TT 64
#define HH 1024
#define EE 512
#define VV 32000
#define NROWS (BB * TT)          // 2048
#define KIN  (EE + HH)           // 1536
#define G3H  (3 * HH)            // 3072
#define NB   128                 // persistent blocks (1/SM, co-resident)
static const size_t BTV = (size_t)BB * TT * VV;  // 65,536,000

// ---------------- device scratch (static; no cudaMalloc anywhere) --------------
__device__ __align__(16) float g_A0[NROWS * KIN];     // dec_in  [2048, 1536]
__device__ __align__(16) float g_gx0[NROWS * G3H];    // x-gates [2048, 3072]
__device__ __align__(16) float g_h1seq[NROWS * HH];   // h1 per (b,t)
__device__ __align__(16) float g_seq[NROWS * HH];     // h2 per (b,t)
__device__ __align__(16) float g_hp[2][BB * HH];      // ping-pong packed h (tf32)
__device__ __align__(16) float g_hp0A[BB * HH];       // packed h0[0]
__device__ __align__(16) float g_hp0B[BB * HH];       // packed h0[1]
__device__ int      g_flag;                           // int32-detect flag (sticky)
__device__ unsigned g_cnt;                            // barrier arrival count
__device__ unsigned g_sense;                          // barrier sense

// ---------------- helpers ------------------------------------------------------
__device__ __forceinline__ uint32_t f2tf(float x) {
    uint32_t u;
    asm("cvt.rna.tf32.f32 %0, %1;" : "=r"(u) : "f"(x));
    return u;
}
__device__ __forceinline__ float f2tff(float x) { return __uint_as_float(f2tf(x)); }

__device__ __forceinline__ void mma_tf32(float c[4], uint32_t a0, uint32_t a1,
                                         uint32_t a2, uint32_t a3,
                                         uint32_t b0, uint32_t b1) {
    asm volatile(
        "mma.sync.aligned.m16n8k8.row.col.f32.tf32.tf32.f32 "
        "{%0,%1,%2,%3}, {%4,%5,%6,%7}, {%8,%9}, {%0,%1,%2,%3};\n"
        : "+f"(c[0]), "+f"(c[1]), "+f"(c[2]), "+f"(c[3])
        : "r"(a0), "r"(a1), "r"(a2), "r"(a3), "r"(b0), "r"(b1));
}

__device__ __forceinline__ float2 ldcg2(const float* p) {
    float2 v;
    asm volatile("ld.global.cg.v2.f32 {%0,%1}, [%2];"
                 : "=f"(v.x), "=f"(v.y) : "l"(p));
    return v;
}

__device__ __forceinline__ float sigm(float x) { return 1.0f / (1.0f + expf(-x)); }

// packed index for h value (b, k): within each 8-k group, order [0,4,1,5,2,6,3,7]
__device__ __forceinline__ int packidx(int b, int k) {
    return (k >> 3) * 256 + b * 8 + ((k & 3) * 2 + ((k >> 2) & 1));
}

// ---------------- replay-safe sense-reversing grid barrier (NB blocks) ---------
__device__ __forceinline__ void grid_bar2() {
    __syncthreads();
    if (threadIdx.x == 0) {
        unsigned s;
        asm volatile("ld.acquire.gpu.u32 %0, [%1];" : "=r"(s) : "l"(&g_sense));
        __threadfence();                 // publish this block's global stores
        unsigned old = atomicAdd(&g_cnt, 1u);
        if (old == NB - 1u) {
            g_cnt = 0u;
            __threadfence();
            asm volatile("st.release.gpu.u32 [%0], %1;" :: "l"(&g_sense), "r"(s ^ 1u));
        } else {
            unsigned v;
            do {
                asm volatile("ld.acquire.gpu.u32 %0, [%1];" : "=r"(v) : "l"(&g_sense));
            } while (v == s);
        }
    }
    __syncthreads();
}

// ---------------- prep: detect token width + build dec_in + pack h0 ------------
// 128 blocks x 1024 threads, one internal grid barrier.
__global__ __launch_bounds__(1024, 1)
void prep_all(const int* __restrict__ Xw, const float* __restrict__ h0,
              const float* __restrict__ emb) {
    int gtid = blockIdx.x * 1024 + threadIdx.x;

    // phase 1: detect int64-vs-int32 (odd words all-zero <=> int64).
    // scan words 1,3,...,2047 (in-bounds for both widths).
    if (gtid < 1024 && Xw[2 * gtid + 1] != 0) atomicOr(&g_flag, 1);
    // pack h0[0]/h0[1] into mma-fragment order, tf32-rounded (no dependency)
    if (gtid < BB * HH) {
        int b = gtid >> 10, k = gtid & 1023;
        int d = packidx(b, k);
        g_hp0A[d] = f2tff(h0[b * HH + k]);
        g_hp0B[d] = f2tff(h0[BB * HH + b * HH + k]);
    }
    grid_bar2();

    // phase 2: build dec_in with per-element token decode
    bool is64 = (g_flag == 0);
    for (int idx = gtid; idx < NROWS * KIN; idx += NB * 1024) {
        int n = idx / KIN;
        int k = idx - n * KIN;
        float v;
        if (k < EE) {
            int tok = is64 ? Xw[2 * n] : Xw[n];
            v = emb[(size_t)tok * EE + k];
        } else {
            int b = n >> 6;                          // n = b*T + t
            v = h0[BB * HH + b * HH + (k - EE)];     // context = h0[1][b]
        }
        g_A0[idx] = v;
    }
}

// ---------------- big tf32 GEMM: 3-stage cp.async pipeline ---------------------
// A smem rows padded to 20 words, B rows to 264 words (conflict-free frag LDS).
#define STAGES 3
#define AW 20
#define BW 264
#define GEMM_SMEM (STAGES * (128 * AW + 16 * BW) * 4)   // 81408 B

__device__ __forceinline__ void cp16(uint32_t dst, const void* src) {
    asm volatile("cp.async.cg.shared.global [%0], [%1], 16;"
                 :: "r"(dst), "l"(src));
}

// sel==0: A=g_A0 -> g_gx0.  sel==1: A=g_seq -> Cext.  sel==2: A=g_h1seq -> g_gx0.
__global__ __launch_bounds__(512, 1)
void gemm_tf32(int sel, const float* __restrict__ Bm, const float* __restrict__ bias,
               float* __restrict__ Cext, int M, int N, int K) {
    const float* A = (sel == 0) ? g_A0 : (sel == 1 ? g_seq : g_h1seq);
    float* C = (sel == 1) ? Cext : g_gx0;

    extern __shared__ float gsm[];
    float* Asm = gsm;                               // [STAGES][128][AW]
    float* Bsm = gsm + STAGES * 128 * AW;           // [STAGES][16][BW]
    uint32_t smem_u32 = (uint32_t)__cvta_generic_to_shared(gsm);
    uint32_t b_u32 = smem_u32 + STAGES * 128 * AW * 4;

    int tid = threadIdx.x;
    int warp = tid >> 5, lane = tid & 31;
    int wm = warp >> 2, wn = warp & 3;
    int lg = lane >> 2, lt = lane & 3;

    int mtiles = M / 128;
    int bm = blockIdx.x % mtiles;                   // M fast-varying: B-tile L2 reuse
    int bn = blockIdx.x / mtiles;
    int m0 = bm * 128, n0 = bn * 256;

    float acc[2][8][4];
#pragma unroll
    for (int a = 0; a < 2; a++)
#pragma unroll
        for (int b = 0; b < 8; b++)
#pragma unroll
            for (int c = 0; c < 4; c++) acc[a][b][c] = 0.0f;

    // cp.async addressing (per thread)
    int am = tid >> 2, akq = (tid & 3) << 2;        // A: 1 chunk / thread
    int brr0 = tid >> 6, bnc0 = (tid & 63) << 2;    // B: 2 chunks / thread
    int brr1 = (tid + 512) >> 6, bnc1 = ((tid + 512) & 63) << 2;

    int Tn = K / 16;

#define ISSUE(st, kk0)                                                           \
    do {                                                                         \
        cp16(smem_u32 + (((st) * 128 + am) * AW + akq) * 4,                      \
             A + (size_t)(m0 + am) * K + (kk0) + akq);                           \
        cp16(b_u32 + (((st) * 16 + brr0) * BW + bnc0) * 4,                       \
             Bm + (size_t)((kk0) + brr0) * N + n0 + bnc0);                       \
        cp16(b_u32 + (((st) * 16 + brr1) * BW + bnc1) * 4,                       \
             Bm + (size_t)((kk0) + brr1) * N + n0 + bnc1);                       \
    } while (0)

    // prologue: stages 0..STAGES-2
    ISSUE(0, 0);
    asm volatile("cp.async.commit_group;");
    ISSUE(1, 16);
    asm volatile("cp.async.commit_group;");

    for (int tI = 0; tI < Tn; tI++) {
        asm volatile("cp.async.wait_group 1;");
        __syncthreads();
        int st = tI % STAGES;

        // issue next stage (overwrites the stage consumed 2 iters ago — safe
        // because the syncthreads above ordered that consumption)
        if (tI + STAGES - 1 < Tn) {
            int ns = (tI + STAGES - 1) % STAGES;
            ISSUE(ns, (tI + STAGES - 1) * 16);
        }
        asm volatile("cp.async.commit_group;");

        const float* As = Asm + st * 128 * AW;
        const float* Bs = Bsm + st * 16 * BW;
#pragma unroll
        for (int kk = 0; kk < 16; kk += 8) {
            uint32_t aF[2][4];
#pragma unroll
            for (int mt = 0; mt < 2; mt++) {
                int mr = wm * 32 + mt * 16 + lg;
                aF[mt][0] = f2tf(As[mr * AW + kk + lt]);
                aF[mt][1] = f2tf(As[(mr + 8) * AW + kk + lt]);
                aF[mt][2] = f2tf(As[mr * AW + kk + lt + 4]);
                aF[mt][3] = f2tf(As[(mr + 8) * AW + kk + lt + 4]);
            }
#pragma unroll
            for (int nt = 0; nt < 8; nt++) {
                int nc2 = wn * 64 + nt * 8 + lg;
                uint32_t b0r = f2tf(Bs[(kk + lt) * BW + nc2]);
                uint32_t b1r = f2tf(Bs[(kk + 4 + lt) * BW + nc2]);
                mma_tf32(acc[0][nt], aF[0][0], aF[0][1], aF[0][2], aF[0][3], b0r, b1r);
                mma_tf32(acc[1][nt], aF[1][0], aF[1][1], aF[1][2], aF[1][3], b0r, b1r);
            }
        }
        __syncthreads();
    }
#undef ISSUE

#pragma unroll
    for (int mt = 0; mt < 2; mt++) {
#pragma unroll
        for (int nt = 0; nt < 8; nt++) {
            int r = m0 + wm * 32 + mt * 16 + lg;
            int c = n0 + wn * 64 + nt * 8 + lt * 2;
            float bv0 = bias[c], bv1 = bias[c + 1];
            float2 v01 = make_float2(acc[mt][nt][0] + bv0, acc[mt][nt][1] + bv1);
            *reinterpret_cast<float2*>(C + (size_t)r * N + c) = v01;
            float2 v23 = make_float2(acc[mt][nt][2] + bv0, acc[mt][nt][3] + bv1);
            *reinterpret_cast<float2*>(C + (size_t)(r + 8) * N + c) = v23;
        }
    }
}

// ---------------- persistent GRU recurrence ------------------------------------
// SMEM: packed tf32 weights (98304 B) + reduce scratch Sp (24576 B).
#define RECUR_SMEM (98304 + 24576)

// load one 8-k group of packed A fragments (4x LDG.64, fully coalesced)
__device__ __forceinline__ void ld_frag(const float* cur, int kg, int lg, int lt,
                                        float2 fr[4]) {
    const float* base = cur + kg * 256 + lt * 2;
    fr[0] = ldcg2(base + lg * 8);
    fr[1] = ldcg2(base + (lg + 8) * 8);
    fr[2] = ldcg2(base + (lg + 16) * 8);
    fr[3] = ldcg2(base + (lg + 24) * 8);
}

// phase 0: U=U0, seq=g_h1seq, s0p=g_hp0A. phase 1: U=U1, seq=g_seq, s0p=g_hp0B.
// (device globals resolved in device code — never pass __device__ symbols from host)
__global__ __launch_bounds__(256, 1)
void gru_recur(int phase, const float* __restrict__ U,
               const float* __restrict__ bh,      // bias row 1 (b[1])
               const float* __restrict__ hinit,   // [32][1024] row-major (exact)
               float* __restrict__ out)           // d_out (final hidden at t=63)
{
    extern __shared__ float smem[];
    float2* sW = reinterpret_cast<float2*>(smem);        // [3*128*32] float2
    float*  sWf = smem;                                  // scalar view
    float*  Sp = smem + 24576;                           // [8][3][32][8]

    float* seq = phase ? g_seq : g_h1seq;
    const float* s0p = phase ? g_hp0B : g_hp0A;

    int tid = threadIdx.x, warp = tid >> 5, lane = tid & 31;
    int lg = lane >> 2, lt = lane & 3;
    int j0 = blockIdx.x * 8;

    // one-time weight gather: coalesced reads (4 full sectors / LDG)
    for (int e = tid; e < 3 * 8192; e += 256) {
        int g = e >> 13;
        int r = e & 8191;
        int k = r >> 3;
        int jj = r & 7;
        float w = U[(size_t)k * G3H + g * HH + j0 + jj];
        int wwarp = k >> 7, kk = k & 127, ks = kk >> 3, c = kk & 7;
        int wlt = c & 3, half = c >> 2;
        int wlane = jj * 4 + wlt;
        sWf[(g * 4096 + (wwarp * 16 + ks) * 32 + wlane) * 2 + half] = f2tff(w);
    }
    __syncthreads();

    // epilogue-invariant operands
    int eb = tid >> 3, ejj = tid & 7;
    int ej = j0 + ejj;
    float bhz = bh[ej], bhr = bh[HH + ej], bhh = bh[2 * HH + ej];
    const float* gxrow = g_gx0 + (size_t)(eb * TT) * G3H;

    for (int t = 0; t < TT; t++) {
        const float* cur = (t == 0) ? s0p : g_hp[t & 1];
        float* nxt = g_hp[(t + 1) & 1];

        // prefetch epilogue operands (hidden under the mma loop)
        const float* gxr = gxrow + (size_t)t * G3H;
        float pgx0 = gxr[ej], pgx1 = gxr[HH + ej], pgx2 = gxr[2 * HH + ej];
        float pho = (t == 0) ? hinit[eb * HH + ej]
                             : seq[((size_t)eb * TT + t - 1) * HH + ej];

        float acc[3][2][4];
#pragma unroll
        for (int g = 0; g < 3; g++)
#pragma unroll
            for (int m = 0; m < 2; m++)
#pragma unroll
                for (int q = 0; q < 4; q++) acc[g][m][q] = 0.0f;

        // depth-4 software pipeline over 16 k-groups
        float2 fr[4][4];
        ld_frag(cur, warp * 16 + 0, lg, lt, fr[0]);
        ld_frag(cur, warp * 16 + 1, lg, lt, fr[1]);
        ld_frag(cur, warp * 16 + 2, lg, lt, fr[2]);
#pragma unroll
        for (int ks = 0; ks < 16; ks++) {
            if (ks + 3 < 16) ld_frag(cur, warp * 16 + ks + 3, lg, lt, fr[(ks + 3) & 3]);
            const float2* f = fr[ks & 3];
            uint32_t a00 = __float_as_uint(f[0].x), a01 = __float_as_uint(f[1].x);
            uint32_t a02 = __float_as_uint(f[0].y), a03 = __float_as_uint(f[1].y);
            uint32_t a10 = __float_as_uint(f[2].x), a11 = __float_as_uint(f[3].x);
            uint32_t a12 = __float_as_uint(f[2].y), a13 = __float_as_uint(f[3].y);
#pragma unroll
            for (int g = 0; g < 3; g++) {
                float2 w = sW[g * 4096 + (warp * 16 + ks) * 32 + lane];
                uint32_t b0 = __float_as_uint(w.x), b1 = __float_as_uint(w.y);
                mma_tf32(acc[g][0], a00, a01, a02, a03, b0, b1);
                mma_tf32(acc[g][1], a10, a11, a12, a13, b0, b1);
            }
        }

        // cross-warp K reduction via SMEM
#pragma unroll
        for (int g = 0; g < 3; g++)
#pragma unroll
            for (int mt = 0; mt < 2; mt++) {
                int rr = mt * 16 + lg;
                float* sb = Sp + ((warp * 3 + g) * 32) * 8;
                sb[rr * 8 + lt * 2]           = acc[g][mt][0];
                sb[rr * 8 + lt * 2 + 1]       = acc[g][mt][1];
                sb[(rr + 8) * 8 + lt * 2]     = acc[g][mt][2];
                sb[(rr + 8) * 8 + lt * 2 + 1] = acc[g][mt][3];
            }
        __syncthreads();

        float sz = 0.f, sr = 0.f, sh = 0.f;
#pragma unroll
        for (int w = 0; w < 8; w++) {
            const float* sb = Sp + (w * 3 * 32) * 8;
            sz += sb[(0 * 32 + eb) * 8 + ejj];
            sr += sb[(1 * 32 + eb) * 8 + ejj];
            sh += sb[(2 * 32 + eb) * 8 + ejj];
        }
        float z = sigm(pgx0 + sz + bhz);
        float r = sigm(pgx1 + sr + bhr);
        float hc = tanhf(pgx2 + r * (sh + bhh));
        float v = z * pho + (1.0f - z) * hc;
        seq[((size_t)eb * TT + t) * HH + ej] = v;                 // exact
        nxt[blockIdx.x * 256 + eb * 8 + ((ejj & 3) * 2 + (ejj >> 2))] = f2tff(v);
        if (t == TT - 1)
            out[BTV + (size_t)phase * BB * HH + eb * HH + ej] = v;

        if (t + 1 < TT) grid_bar2();
    }
}

// ---------------- launch -------------------------------------------------------
extern "C" void kernel_launch(void* const* d_in, const int* in_sizes, int n_in,
                              void* d_out, int out_size) {
    (void)in_sizes; (void)n_in; (void)out_size;
    const int*   X   = (const int*)d_in[0];
    const float* h0  = (const float*)d_in[1];
    const float* emb = (const float*)d_in[2];
    const float* W0  = (const float*)d_in[3];
    const float* U0  = (const float*)d_in[4];
    const float* b0  = (const float*)d_in[5];
    const float* W1  = (const float*)d_in[6];
    const float* U1  = (const float*)d_in[7];
    const float* b1  = (const float*)d_in[8];
    const float* Wd  = (const float*)d_in[9];
    const float* bd  = (const float*)d_in[10];
    float* out = (float*)d_out;

    cudaFuncSetAttribute(gru_recur, cudaFuncAttributeMaxDynamicSharedMemorySize,
                         RECUR_SMEM);
    cudaFuncSetAttribute(gemm_tf32, cudaFuncAttributeMaxDynamicSharedMemorySize,
                         GEMM_SMEM);

    // [0] detect + dec_in + h0 pack (internal grid barrier)
    prep_all<<<NB, 1024>>>(X, h0, emb);

    // [1] gx0 = dec_in @ W0 + b0[0]   (M=2048, N=3072, K=1536)
    gemm_tf32<<<(NROWS / 128) * (G3H / 256), 512, GEMM_SMEM>>>(
        0, W0, b0, nullptr, NROWS, G3H, KIN);

    // [2] phase A: layer-0 recurrence
    gru_recur<<<NB, 256, RECUR_SMEM>>>(0, U0, b0 + G3H, h0, out);

    // [3] gx1 = h1_seq @ W1 + b1[0]   (M=2048, N=3072, K=1024)
    gemm_tf32<<<(NROWS / 128) * (G3H / 256), 512, GEMM_SMEM>>>(
        2, W1, b1, nullptr, NROWS, G3H, HH);

    // [4] phase B: layer-1 recurrence
    gru_recur<<<NB, 256, RECUR_SMEM>>>(1, U1, b1 + G3H, h0 + BB * HH, out);

    // [5] logits = seq @ Wd + bd -> d_out   (M=2048, N=32000, K=1024)  <- ncu -s 5
    gemm_tf32<<<(NROWS / 128) * (VV / 256), 512, GEMM_SMEM>>>(
        1, Wd, bd, out, NROWS, VV, HH);
}

// round 14
// speedup vs baseline: 1.5658x; 1.5658x over previous
#include <cuda_runtime.h>
#include <cuda_bf16.h>
#include <math.h>
#include <stdint.h>

// Problem constants
#define BB 32
#define TT 64
#define HH 1024
#define EE 512
#define VV 32000
#define NROWS (BB * TT)          // 2048
#define KIN  (EE + HH)           // 1536
#define G3H  (3 * HH)            // 3072
#define NB   128                 // persistent blocks (1/SM, co-resident)
static const size_t BTV = (size_t)BB * TT * VV;  // 65,536,000

// ---------------- device scratch (static; no cudaMalloc anywhere) --------------
__device__ __align__(16) float g_A0[NROWS * KIN];     // dec_in, tf32-rounded
__device__ __align__(16) float g_gx0[NROWS * G3H];    // x-gates (exact fp32)
__device__ __align__(16) float g_h1seq[NROWS * HH];   // h1 exact
__device__ __align__(16) float g_seq[NROWS * HH];     // h2 exact
__device__ __align__(16) float g_h1r[NROWS * HH];     // h1 tf32-rounded (GEMM A)
__device__ __align__(16) float g_seqr[NROWS * HH];    // h2 tf32-rounded (GEMM A)
__device__ __align__(16) float g_hp[2][BB * HH];      // ping-pong packed h (tf32)
__device__ __align__(16) float g_hp0A[BB * HH];       // packed h0[0]
__device__ __align__(16) float g_hp0B[BB * HH];       // packed h0[1]
__device__ __align__(16) float g_W0r[KIN * G3H];      // tf32-rounded weights
__device__ __align__(16) float g_W1r[HH * G3H];
__device__ __align__(16) float g_Wdr[(size_t)HH * VV];
__device__ int      g_flag;                           // int32-detect flag (sticky)
__device__ unsigned g_cnt;                            // barrier arrival count
__device__ unsigned g_sense;                          // barrier sense

// ---------------- helpers ------------------------------------------------------
__device__ __forceinline__ uint32_t f2tf(float x) {
    uint32_t u;
    asm("cvt.rna.tf32.f32 %0, %1;" : "=r"(u) : "f"(x));
    return u;
}
__device__ __forceinline__ float f2tff(float x) { return __uint_as_float(f2tf(x)); }

__device__ __forceinline__ void mma_tf32(float c[4], uint32_t a0, uint32_t a1,
                                         uint32_t a2, uint32_t a3,
                                         uint32_t b0, uint32_t b1) {
    asm volatile(
        "mma.sync.aligned.m16n8k8.row.col.f32.tf32.tf32.f32 "
        "{%0,%1,%2,%3}, {%4,%5,%6,%7}, {%8,%9}, {%0,%1,%2,%3};\n"
        : "+f"(c[0]), "+f"(c[1]), "+f"(c[2]), "+f"(c[3])
        : "r"(a0), "r"(a1), "r"(a2), "r"(a3), "r"(b0), "r"(b1));
}

__device__ __forceinline__ float2 ldcg2(const float* p) {
    float2 v;
    asm volatile("ld.global.cg.v2.f32 {%0,%1}, [%2];"
                 : "=f"(v.x), "=f"(v.y) : "l"(p));
    return v;
}

__device__ __forceinline__ float sigm(float x) { return 1.0f / (1.0f + expf(-x)); }

// packed index for h value (b, k): within each 8-k group, order [0,4,1,5,2,6,3,7]
__device__ __forceinline__ int packidx(int b, int k) {
    return (k >> 3) * 256 + b * 8 + ((k & 3) * 2 + ((k >> 2) & 1));
}

// ---------------- replay-safe sense-reversing grid barrier (NB blocks) ---------
__device__ __forceinline__ void grid_bar2() {
    __syncthreads();
    if (threadIdx.x == 0) {
        unsigned s;
        asm volatile("ld.acquire.gpu.u32 %0, [%1];" : "=r"(s) : "l"(&g_sense));
        __threadfence();                 // publish this block's global stores
        unsigned old = atomicAdd(&g_cnt, 1u);
        if (old == NB - 1u) {
            g_cnt = 0u;
            __threadfence();
            asm volatile("st.release.gpu.u32 [%0], %1;" :: "l"(&g_sense), "r"(s ^ 1u));
        } else {
            unsigned v;
            do {
                asm volatile("ld.acquire.gpu.u32 %0, [%1];" : "=r"(v) : "l"(&g_sense));
            } while (v == s);
        }
    }
    __syncthreads();
}

// ---------------- prep: detect tokens, build dec_in, pack h0, round weights ----
// 128 blocks x 1024 threads, one internal grid barrier.
__global__ __launch_bounds__(1024, 1)
void prep_all(const int* __restrict__ Xw, const float* __restrict__ h0,
              const float* __restrict__ emb, const float* __restrict__ W0,
              const float* __restrict__ W1, const float* __restrict__ Wd) {
    int gtid = blockIdx.x * 1024 + threadIdx.x;
    const int GT = NB * 1024;

    // phase 1: detect int64-vs-int32 (odd words all-zero <=> int64)
    if (gtid < 1024 && Xw[2 * gtid + 1] != 0) atomicOr(&g_flag, 1);
    // pack h0 into mma-fragment order, tf32-rounded
    if (gtid < BB * HH) {
        int b = gtid >> 10, k = gtid & 1023;
        int d = packidx(b, k);
        g_hp0A[d] = f2tff(h0[b * HH + k]);
        g_hp0B[d] = f2tff(h0[BB * HH + b * HH + k]);
    }
    // weight rounding (no ordering dependency; overlaps barrier wait)
    for (int i = gtid; i < KIN * G3H; i += GT) g_W0r[i] = f2tff(W0[i]);
    for (int i = gtid; i < HH * G3H; i += GT)  g_W1r[i] = f2tff(W1[i]);
    for (size_t i = gtid; i < (size_t)HH * VV; i += GT) g_Wdr[i] = f2tff(Wd[i]);
    grid_bar2();

    // phase 2: build dec_in (pre-rounded; used only as GEMM A operand)
    bool is64 = (g_flag == 0);
    for (int idx = gtid; idx < NROWS * KIN; idx += GT) {
        int n = idx / KIN;
        int k = idx - n * KIN;
        float v;
        if (k < EE) {
            int tok = is64 ? Xw[2 * n] : Xw[n];
            v = emb[(size_t)tok * EE + k];
        } else {
            int b = n >> 6;                          // n = b*T + t
            v = h0[BB * HH + b * HH + (k - EE)];     // context = h0[1][b]
        }
        g_A0[idx] = f2tff(v);
    }
}

// ---------------- big tf32 GEMM: 3-stage cp.async, pre-rounded operands --------
// A smem rows padded to 20 words, B rows to 264 words (conflict-free frag LDS).
#define STAGES 3
#define AW 20
#define BW 264
#define GEMM_SMEM (STAGES * (128 * AW + 16 * BW) * 4)   // 81408 B

__device__ __forceinline__ void cp16(uint32_t dst, const void* src) {
    asm volatile("cp.async.cg.shared.global [%0], [%1], 16;"
                 :: "r"(dst), "l"(src));
}

// sel==0: gx0 = A0 @ W0r.  sel==1: logits = seqr @ Wdr -> Cext.
// sel==2: gx1 = h1r @ W1r.  (A and B resolved IN DEVICE CODE.)
__global__ __launch_bounds__(512, 1)
void gemm_tf32(int sel, const float* __restrict__ bias,
               float* __restrict__ Cext, int M, int N, int K) {
    const float* A  = (sel == 0) ? g_A0  : (sel == 1 ? g_seqr : g_h1r);
    const float* Bm = (sel == 0) ? g_W0r : (sel == 1 ? g_Wdr  : g_W1r);
    float* C = (sel == 1) ? Cext : g_gx0;

    extern __shared__ float gsm[];
    float* Asm = gsm;                               // [STAGES][128][AW]
    float* Bsm = gsm + STAGES * 128 * AW;           // [STAGES][16][BW]
    uint32_t smem_u32 = (uint32_t)__cvta_generic_to_shared(gsm);
    uint32_t b_u32 = smem_u32 + STAGES * 128 * AW * 4;

    int tid = threadIdx.x;
    int warp = tid >> 5, lane = tid & 31;
    int wm = warp >> 2, wn = warp & 3;
    int lg = lane >> 2, lt = lane & 3;

    int mtiles = M / 128;
    int bm = blockIdx.x % mtiles;                   // M fast-varying: B-tile L2 reuse
    int bn = blockIdx.x / mtiles;
    int m0 = bm * 128, n0 = bn * 256;

    float acc[2][8][4];
#pragma unroll
    for (int a = 0; a < 2; a++)
#pragma unroll
        for (int b = 0; b < 8; b++)
#pragma unroll
            for (int c = 0; c < 4; c++) acc[a][b][c] = 0.0f;

    int am = tid >> 2, akq = (tid & 3) << 2;        // A: 1 chunk / thread
    int brr0 = tid >> 6, bnc0 = (tid & 63) << 2;    // B: 2 chunks / thread
    int brr1 = (tid + 512) >> 6, bnc1 = ((tid + 512) & 63) << 2;

    int Tn = K / 16;

#define ISSUE(st, kk0)                                                           \
    do {                                                                         \
        cp16(smem_u32 + (((st) * 128 + am) * AW + akq) * 4,                      \
             A + (size_t)(m0 + am) * K + (kk0) + akq);                           \
        cp16(b_u32 + (((st) * 16 + brr0) * BW + bnc0) * 4,                       \
             Bm + (size_t)((kk0) + brr0) * N + n0 + bnc0);                       \
        cp16(b_u32 + (((st) * 16 + brr1) * BW + bnc1) * 4,                       \
             Bm + (size_t)((kk0) + brr1) * N + n0 + bnc1);                       \
    } while (0)

    ISSUE(0, 0);
    asm volatile("cp.async.commit_group;");
    ISSUE(1, 16);
    asm volatile("cp.async.commit_group;");

    for (int tI = 0; tI < Tn; tI++) {
        asm volatile("cp.async.wait_group 1;");
        __syncthreads();
        int st = tI % STAGES;

        if (tI + STAGES - 1 < Tn) {
            int ns = (tI + STAGES - 1) % STAGES;
            ISSUE(ns, (tI + STAGES - 1) * 16);
        }
        asm volatile("cp.async.commit_group;");

        const float* As = Asm + st * 128 * AW;
        const float* Bs = Bsm + st * 16 * BW;
#pragma unroll
        for (int kk = 0; kk < 16; kk += 8) {
            uint32_t aF[2][4];
#pragma unroll
            for (int mt = 0; mt < 2; mt++) {
                int mr = wm * 32 + mt * 16 + lg;
                aF[mt][0] = __float_as_uint(As[mr * AW + kk + lt]);
                aF[mt][1] = __float_as_uint(As[(mr + 8) * AW + kk + lt]);
                aF[mt][2] = __float_as_uint(As[mr * AW + kk + lt + 4]);
                aF[mt][3] = __float_as_uint(As[(mr + 8) * AW + kk + lt + 4]);
            }
#pragma unroll
            for (int nt = 0; nt < 8; nt++) {
                int nc2 = wn * 64 + nt * 8 + lg;
                uint32_t b0r = __float_as_uint(Bs[(kk + lt) * BW + nc2]);
                uint32_t b1r = __float_as_uint(Bs[(kk + 4 + lt) * BW + nc2]);
                mma_tf32(acc[0][nt], aF[0][0], aF[0][1], aF[0][2], aF[0][3], b0r, b1r);
                mma_tf32(acc[1][nt], aF[1][0], aF[1][1], aF[1][2], aF[1][3], b0r, b1r);
            }
        }
        __syncthreads();
    }
#undef ISSUE

#pragma unroll
    for (int mt = 0; mt < 2; mt++) {
#pragma unroll
        for (int nt = 0; nt < 8; nt++) {
            int r = m0 + wm * 32 + mt * 16 + lg;
            int c = n0 + wn * 64 + nt * 8 + lt * 2;
            float bv0 = bias[c], bv1 = bias[c + 1];
            float2 v01 = make_float2(acc[mt][nt][0] + bv0, acc[mt][nt][1] + bv1);
            *reinterpret_cast<float2*>(C + (size_t)r * N + c) = v01;
            float2 v23 = make_float2(acc[mt][nt][2] + bv0, acc[mt][nt][3] + bv1);
            *reinterpret_cast<float2*>(C + (size_t)(r + 8) * N + c) = v23;
        }
    }
}

// ---------------- persistent GRU recurrence ------------------------------------
// SMEM: packed tf32 weights (98304 B) + reduce scratch Sp (24576 B).
#define RECUR_SMEM (98304 + 24576)

// load one 8-k group of packed A fragments (4x LDG.64, fully coalesced)
__device__ __forceinline__ void ld_frag(const float* cur, int kg, int lg, int lt,
                                        float2 fr[4]) {
    const float* base = cur + kg * 256 + lt * 2;
    fr[0] = ldcg2(base + lg * 8);
    fr[1] = ldcg2(base + (lg + 8) * 8);
    fr[2] = ldcg2(base + (lg + 16) * 8);
    fr[3] = ldcg2(base + (lg + 24) * 8);
}

// phase 0: U=U0, seq=g_h1seq(+g_h1r), s0p=g_hp0A.
// phase 1: U=U1, seq=g_seq(+g_seqr), s0p=g_hp0B.
__global__ __launch_bounds__(256, 1)
void gru_recur(int phase, const float* __restrict__ U,
               const float* __restrict__ bh,      // bias row 1 (b[1])
               const float* __restrict__ hinit,   // [32][1024] row-major (exact)
               float* __restrict__ out)           // d_out (final hidden at t=63)
{
    extern __shared__ float smem[];
    float2* sW = reinterpret_cast<float2*>(smem);        // [3*128*32] float2
    float*  sWf = smem;                                  // scalar view
    float*  Sp = smem + 24576;                           // [8][3][32][8]

    float* seq  = phase ? g_seq  : g_h1seq;
    float* seqr = phase ? g_seqr : g_h1r;
    const float* s0p = phase ? g_hp0B : g_hp0A;

    int tid = threadIdx.x, warp = tid >> 5, lane = tid & 31;
    int lg = lane >> 2, lt = lane & 3;
    int j0 = blockIdx.x * 8;

    // one-time weight gather: coalesced reads (4 full sectors / LDG)
    for (int e = tid; e < 3 * 8192; e += 256) {
        int g = e >> 13;
        int r = e & 8191;
        int k = r >> 3;
        int jj = r & 7;
        float w = U[(size_t)k * G3H + g * HH + j0 + jj];
        int wwarp = k >> 7, kk = k & 127, ks = kk >> 3, c = kk & 7;
        int wlt = c & 3, half = c >> 2;
        int wlane = jj * 4 + wlt;
        sWf[(g * 4096 + (wwarp * 16 + ks) * 32 + wlane) * 2 + half] = f2tff(w);
    }
    __syncthreads();

    // epilogue-invariant operands
    int eb = tid >> 3, ejj = tid & 7;
    int ej = j0 + ejj;
    float bhz = bh[ej], bhr = bh[HH + ej], bhh = bh[2 * HH + ej];
    const float* gxrow = g_gx0 + (size_t)(eb * TT) * G3H;

    for (int t = 0; t < TT; t++) {
        const float* cur = (t == 0) ? s0p : g_hp[t & 1];
        float* nxt = g_hp[(t + 1) & 1];

        // prefetch epilogue operands (hidden under the mma loop)
        const float* gxr = gxrow + (size_t)t * G3H;
        float pgx0 = gxr[ej], pgx1 = gxr[HH + ej], pgx2 = gxr[2 * HH + ej];
        float pho = (t == 0) ? hinit[eb * HH + ej]
                             : seq[((size_t)eb * TT + t - 1) * HH + ej];

        float acc[3][2][4];
#pragma unroll
        for (int g = 0; g < 3; g++)
#pragma unroll
            for (int m = 0; m < 2; m++)
#pragma unroll
                for (int q = 0; q < 4; q++) acc[g][m][q] = 0.0f;

        // depth-4 software pipeline over 16 k-groups
        float2 fr[4][4];
        ld_frag(cur, warp * 16 + 0, lg, lt, fr[0]);
        ld_frag(cur, warp * 16 + 1, lg, lt, fr[1]);
        ld_frag(cur, warp * 16 + 2, lg, lt, fr[2]);
#pragma unroll
        for (int ks = 0; ks < 16; ks++) {
            if (ks + 3 < 16) ld_frag(cur, warp * 16 + ks + 3, lg, lt, fr[(ks + 3) & 3]);
            const float2* f = fr[ks & 3];
            uint32_t a00 = __float_as_uint(f[0].x), a01 = __float_as_uint(f[1].x);
            uint32_t a02 = __float_as_uint(f[0].y), a03 = __float_as_uint(f[1].y);
            uint32_t a10 = __float_as_uint(f[2].x), a11 = __float_as_uint(f[3].x);
            uint32_t a12 = __float_as_uint(f[2].y), a13 = __float_as_uint(f[3].y);
#pragma unroll
            for (int g = 0; g < 3; g++) {
                float2 w = sW[g * 4096 + (warp * 16 + ks) * 32 + lane];
                uint32_t b0 = __float_as_uint(w.x), b1 = __float_as_uint(w.y);
                mma_tf32(acc[g][0], a00, a01, a02, a03, b0, b1);
                mma_tf32(acc[g][1], a10, a11, a12, a13, b0, b1);
            }
        }

        // cross-warp K reduction via SMEM
#pragma unroll
        for (int g = 0; g < 3; g++)
#pragma unroll
            for (int mt = 0; mt < 2; mt++) {
                int rr = mt * 16 + lg;
                float* sb = Sp + ((warp * 3 + g) * 32) * 8;
                sb[rr * 8 + lt * 2]           = acc[g][mt][0];
                sb[rr * 8 + lt * 2 + 1]       = acc[g][mt][1];
                sb[(rr + 8) * 8 + lt * 2]     = acc[g][mt][2];
                sb[(rr + 8) * 8 + lt * 2 + 1] = acc[g][mt][3];
            }
        __syncthreads();

        float sz = 0.f, sr = 0.f, sh = 0.f;
#pragma unroll
        for (int w = 0; w < 8; w++) {
            const float* sb = Sp + (w * 3 * 32) * 8;
            sz += sb[(0 * 32 + eb) * 8 + ejj];
            sr += sb[(1 * 32 + eb) * 8 + ejj];
            sh += sb[(2 * 32 + eb) * 8 + ejj];
        }
        float z = sigm(pgx0 + sz + bhz);
        float r = sigm(pgx1 + sr + bhr);
        float hc = tanhf(pgx2 + r * (sh + bhh));
        float v = z * pho + (1.0f - z) * hc;
        float vr = f2tff(v);
        seq[((size_t)eb * TT + t) * HH + ej]  = v;   // exact (ho path + hidden out)
        seqr[((size_t)eb * TT + t) * HH + ej] = vr;  // rounded (GEMM A operand)
        nxt[blockIdx.x * 256 + eb * 8 + ((ejj & 3) * 2 + (ejj >> 2))] = vr;
        if (t == TT - 1)
            out[BTV + (size_t)phase * BB * HH + eb * HH + ej] = v;

        if (t + 1 < TT) grid_bar2();
    }
}

// ---------------- launch -------------------------------------------------------
extern "C" void kernel_launch(void* const* d_in, const int* in_sizes, int n_in,
                              void* d_out, int out_size) {
    (void)in_sizes; (void)n_in; (void)out_size;
    const int*   X   = (const int*)d_in[0];
    const float* h0  = (const float*)d_in[1];
    const float* emb = (const float*)d_in[2];
    const float* W0  = (const float*)d_in[3];
    const float* U0  = (const float*)d_in[4];
    const float* b0  = (const float*)d_in[5];
    const float* W1  = (const float*)d_in[6];
    const float* U1  = (const float*)d_in[7];
    const float* b1  = (const float*)d_in[8];
    const float* Wd  = (const float*)d_in[9];
    const float* bd  = (const float*)d_in[10];
    float* out = (float*)d_out;

    cudaFuncSetAttribute(gru_recur, cudaFuncAttributeMaxDynamicSharedMemorySize,
                         RECUR_SMEM);
    cudaFuncSetAttribute(gemm_tf32, cudaFuncAttributeMaxDynamicSharedMemorySize,
                         GEMM_SMEM);

    // [0] detect + dec_in + h0 pack + weight rounding (internal grid barrier)
    prep_all<<<NB, 1024>>>(X, h0, emb, W0, W1, Wd);

    // [1] gx0 = dec_in @ W0 + b0[0]   (M=2048, N=3072, K=1536)
    gemm_tf32<<<(NROWS / 128) * (G3H / 256), 512, GEMM_SMEM>>>(
        0, b0, nullptr, NROWS, G3H, KIN);

    // [2] phase A: layer-0 recurrence
    gru_recur<<<NB, 256, RECUR_SMEM>>>(0, U0, b0 + G3H, h0, out);

    // [3] gx1 = h1_seq @ W1 + b1[0]   (M=2048, N=3072, K=1024)
    gemm_tf32<<<(NROWS / 128) * (G3H / 256), 512, GEMM_SMEM>>>(
        2, b1, nullptr, NROWS, G3H, HH);

    // [4] phase B: layer-1 recurrence
    gru_recur<<<NB, 256, RECUR_SMEM>>>(1, U1, b1 + G3H, h0 + BB * HH, out);

    // [5] logits = seqr @ Wdr + bd -> d_out  (M=2048, N=32000, K=1024)  <- ncu -s 5
    gemm_tf32<<<(NROWS / 128) * (VV / 256), 512, GEMM_SMEM>>>(
        1, bd, out, NROWS, VV, HH);
}

// round 16
// speedup vs baseline: 2.0656x; 1.3192x over previous
#include <cuda_runtime.h>
#include <cuda_fp16.h>
#include <math.h>
#include <stdint.h>

// Problem constants
#define BB 32
#define TT 64
#define HH 1024
#define EE 512
#define VV 32000
#define NROWS (BB * TT)          // 2048
#define KIN  (EE + HH)           // 1536
#define G3H  (3 * HH)            // 3072
#define NB   128                 // persistent blocks (1/SM, co-resident)
static const size_t BTV = (size_t)BB * TT * VV;  // 65,536,000

// ---------------- device scratch (static; no cudaMalloc anywhere) --------------
__device__ __align__(16) __half g_A0h[NROWS * KIN];    // dec_in, fp16
__device__ __align__(16) float  g_gx0[NROWS * G3H];    // x-gates (exact fp32)
__device__ __align__(16) float  g_h1seq[NROWS * HH];   // h1 exact
__device__ __align__(16) float  g_seq[NROWS * HH];     // h2 exact
__device__ __align__(16) __half g_h1h[NROWS * HH];     // h1 fp16 (GEMM A)
__device__ __align__(16) __half g_seqh[NROWS * HH];    // h2 fp16 (GEMM A)
__device__ __align__(16) float  g_hp[2][BB * HH];      // ping-pong packed h (tf32)
__device__ __align__(16) float  g_hp0A[BB * HH];       // packed h0[0]
__device__ __align__(16) float  g_hp0B[BB * HH];       // packed h0[1]
__device__ __align__(16) __half g_W0h[(size_t)G3H * KIN];  // W0^T fp16 [n][k]
__device__ __align__(16) __half g_W1h[(size_t)G3H * HH];   // W1^T fp16 [n][k]
__device__ __align__(16) __half g_Wdh[(size_t)VV * HH];    // Wd^T fp16 [n][k]
__device__ int      g_flag;                            // int32-detect flag
__device__ unsigned g_cnt;                             // barrier arrival count
__device__ unsigned g_sense;                           // barrier sense

// ---------------- helpers ------------------------------------------------------
__device__ __forceinline__ uint32_t f2tf(float x) {
    uint32_t u;
    asm("cvt.rna.tf32.f32 %0, %1;" : "=r"(u) : "f"(x));
    return u;
}
__device__ __forceinline__ float f2tff(float x) { return __uint_as_float(f2tf(x)); }

__device__ __forceinline__ void mma_tf32(float c[4], uint32_t a0, uint32_t a1,
                                         uint32_t a2, uint32_t a3,
                                         uint32_t b0, uint32_t b1) {
    asm volatile(
        "mma.sync.aligned.m16n8k8.row.col.f32.tf32.tf32.f32 "
        "{%0,%1,%2,%3}, {%4,%5,%6,%7}, {%8,%9}, {%0,%1,%2,%3};\n"
        : "+f"(c[0]), "+f"(c[1]), "+f"(c[2]), "+f"(c[3])
        : "r"(a0), "r"(a1), "r"(a2), "r"(a3), "r"(b0), "r"(b1));
}

__device__ __forceinline__ void mma_f16(float c[4], uint32_t a0, uint32_t a1,
                                        uint32_t a2, uint32_t a3,
                                        uint32_t b0, uint32_t b1) {
    asm volatile(
        "mma.sync.aligned.m16n8k16.row.col.f32.f16.f16.f32 "
        "{%0,%1,%2,%3}, {%4,%5,%6,%7}, {%8,%9}, {%0,%1,%2,%3};\n"
        : "+f"(c[0]), "+f"(c[1]), "+f"(c[2]), "+f"(c[3])
        : "r"(a0), "r"(a1), "r"(a2), "r"(a3), "r"(b0), "r"(b1));
}

__device__ __forceinline__ float2 ldcg2(const float* p) {
    float2 v;
    asm volatile("ld.global.cg.v2.f32 {%0,%1}, [%2];"
                 : "=f"(v.x), "=f"(v.y) : "l"(p));
    return v;
}

__device__ __forceinline__ float sigm(float x) { return 1.0f / (1.0f + expf(-x)); }

// packed index for h value (b, k): within each 8-k group, order [0,4,1,5,2,6,3,7]
__device__ __forceinline__ int packidx(int b, int k) {
    return (k >> 3) * 256 + b * 8 + ((k & 3) * 2 + ((k >> 2) & 1));
}

// ---------------- replay-safe sense-reversing grid barrier (NB blocks) ---------
__device__ __forceinline__ void grid_bar2() {
    __syncthreads();
    if (threadIdx.x == 0) {
        unsigned s;
        asm volatile("ld.acquire.gpu.u32 %0, [%1];" : "=r"(s) : "l"(&g_sense));
        __threadfence();                 // publish this block's global stores
        unsigned old = atomicAdd(&g_cnt, 1u);
        if (old == NB - 1u) {
            g_cnt = 0u;
            __threadfence();
            asm volatile("st.release.gpu.u32 [%0], %1;" :: "l"(&g_sense), "r"(s ^ 1u));
        } else {
            unsigned v;
            do {
                asm volatile("ld.acquire.gpu.u32 %0, [%1];" : "=r"(v) : "l"(&g_sense));
            } while (v == s);
        }
    }
    __syncthreads();
}

// ---------------- prep: detect tokens, build dec_in (fp16), pack h0 ------------
__global__ __launch_bounds__(1024, 1)
void prep_all(const int* __restrict__ Xw, const float* __restrict__ h0,
              const float* __restrict__ emb) {
    int gtid = blockIdx.x * 1024 + threadIdx.x;
    const int GT = NB * 1024;

    // detect int64-vs-int32 (odd words all-zero <=> int64)
    if (gtid < 1024 && Xw[2 * gtid + 1] != 0) atomicOr(&g_flag, 1);
    // pack h0 into mma-fragment order, tf32-rounded
    if (gtid < BB * HH) {
        int b = gtid >> 10, k = gtid & 1023;
        int d = packidx(b, k);
        g_hp0A[d] = f2tff(h0[b * HH + k]);
        g_hp0B[d] = f2tff(h0[BB * HH + b * HH + k]);
    }
    grid_bar2();

    bool is64 = (g_flag == 0);
    for (int idx = gtid; idx < NROWS * KIN; idx += GT) {
        int n = idx / KIN;
        int k = idx - n * KIN;
        float v;
        if (k < EE) {
            int tok = is64 ? Xw[2 * n] : Xw[n];
            v = emb[(size_t)tok * EE + k];
        } else {
            int b = n >> 6;                          // n = b*T + t
            v = h0[BB * HH + b * HH + (k - EE)];     // context = h0[1][b]
        }
        g_A0h[idx] = __float2half(v);
    }
}

// ---------------- weight transpose: S[K][N] fp32 -> D[N][K] fp16 ---------------
// sel: 0=W0h, 1=W1h, 2=Wdh (destinations resolved in device code).
__global__ __launch_bounds__(256)
void transpose_h(const float* __restrict__ S, int sel, int K, int N) {
    __half* D = (sel == 0) ? g_W0h : (sel == 1 ? g_W1h : g_Wdh);
    __shared__ float tile[32][33];
    int n0 = blockIdx.x * 32, k0 = blockIdx.y * 32;
    int tx = threadIdx.x & 31, ty = threadIdx.x >> 5;   // 32 x 8
    for (int r = ty; r < 32; r += 8)
        tile[r][tx] = S[(size_t)(k0 + r) * N + n0 + tx];
    __syncthreads();
    for (int r = ty; r < 32; r += 8)
        D[(size_t)(n0 + r) * K + k0 + tx] = __float2half(tile[tx][r]);
}

// ---------------- fp16 GEMM: 4-stage cp.async, m16n8k16, fp32 accum ------------
// A [M][K] half row-major; B stored transposed [N][K] half. C fp32 + bias.
// smem rows padded to 40 halves (80 B): bank pattern 20*lg+lt -> conflict-free.
#define STAGES 4
#define AWH 40
#define A_ST (128 * AWH)                 // halves per A stage = 5120
#define B_ST (256 * AWH)                 // halves per B stage = 10240
#define GEMM_SMEM (STAGES * (A_ST + B_ST) * 2)   // 122880 B

__device__ __forceinline__ void cp16(uint32_t dst, const void* src) {
    asm volatile("cp.async.cg.shared.global [%0], [%1], 16;"
                 :: "r"(dst), "l"(src));
}

// sel==0: gx0 = A0h @ W0h.  sel==1: logits = seqh @ Wdh -> Cext.
// sel==2: gx1 = h1h @ W1h.  (A and B resolved IN DEVICE CODE.)
__global__ __launch_bounds__(512, 1)
void gemm_f16(int sel, const float* __restrict__ bias,
              float* __restrict__ Cext, int M, int N, int K) {
    const __half* A  = (sel == 0) ? g_A0h : (sel == 1 ? g_seqh : g_h1h);
    const __half* Bm = (sel == 0) ? g_W0h : (sel == 1 ? g_Wdh  : g_W1h);
    float* C = (sel == 1) ? Cext : g_gx0;

    extern __shared__ __half hsm[];
    __half* Asm = hsm;                               // [STAGES][128][AWH]
    __half* Bsm = hsm + STAGES * A_ST;               // [STAGES][256][AWH]
    uint32_t a_u32 = (uint32_t)__cvta_generic_to_shared(hsm);
    uint32_t b_u32 = a_u32 + STAGES * A_ST * 2;

    int tid = threadIdx.x;
    int warp = tid >> 5, lane = tid & 31;
    int wm = warp >> 2, wn = warp & 3;               // 4x4 warp grid, 32x64/warp
    int lg = lane >> 2, lt = lane & 3;

    int mtiles = M / 128;
    int bm = blockIdx.x % mtiles;                    // M fast-varying: B-tile L2 reuse
    int bn = blockIdx.x / mtiles;
    int m0 = bm * 128, n0 = bn * 256;

    float acc[2][8][4];
#pragma unroll
    for (int a = 0; a < 2; a++)
#pragma unroll
        for (int b = 0; b < 8; b++)
#pragma unroll
            for (int c = 0; c < 4; c++) acc[a][b][c] = 0.0f;

    // cp.async addressing: A 512 chunks (1/thread), B 1024 chunks (2/thread)
    int arow = tid >> 2, ac8 = (tid & 3) << 3;       // A: row 0..127, chunk of 8 halves
    int brow = tid >> 2, bc8 = (tid & 3) << 3;       // B: rows brow and brow+128

    int Tn = K / 32;

#define ISSUE(st, kk0)                                                            \
    do {                                                                          \
        cp16(a_u32 + ((st) * A_ST + arow * AWH + ac8) * 2,                        \
             A + (size_t)(m0 + arow) * K + (kk0) + ac8);                          \
        cp16(b_u32 + ((st) * B_ST + brow * AWH + bc8) * 2,                        \
             Bm + (size_t)(n0 + brow) * K + (kk0) + bc8);                         \
        cp16(b_u32 + ((st) * B_ST + (brow + 128) * AWH + bc8) * 2,                \
             Bm + (size_t)(n0 + brow + 128) * K + (kk0) + bc8);                   \
    } while (0)

    ISSUE(0, 0);
    asm volatile("cp.async.commit_group;");
    ISSUE(1, 32);
    asm volatile("cp.async.commit_group;");
    ISSUE(2, 64);
    asm volatile("cp.async.commit_group;");

    for (int tI = 0; tI < Tn; tI++) {
        asm volatile("cp.async.wait_group 2;");
        __syncthreads();
        int st = tI & (STAGES - 1);

        if (tI + STAGES - 1 < Tn) {
            int ns = (tI + STAGES - 1) & (STAGES - 1);
            ISSUE(ns, (tI + STAGES - 1) * 32);
        }
        asm volatile("cp.async.commit_group;");

        const __half* As = Asm + st * A_ST;
        const __half* Bs = Bsm + st * B_ST;
#pragma unroll
        for (int kk = 0; kk < 32; kk += 16) {
            uint32_t aF[2][4];
#pragma unroll
            for (int mt = 0; mt < 2; mt++) {
                int mr = wm * 32 + mt * 16 + lg;
                aF[mt][0] = *(const uint32_t*)(As + mr * AWH + kk + 2 * lt);
                aF[mt][1] = *(const uint32_t*)(As + (mr + 8) * AWH + kk + 2 * lt);
                aF[mt][2] = *(const uint32_t*)(As + mr * AWH + kk + 2 * lt + 8);
                aF[mt][3] = *(const uint32_t*)(As + (mr + 8) * AWH + kk + 2 * lt + 8);
            }
#pragma unroll
            for (int nt = 0; nt < 8; nt++) {
                int n = wn * 64 + nt * 8 + lg;
                uint32_t b0 = *(const uint32_t*)(Bs + n * AWH + kk + 2 * lt);
                uint32_t b1 = *(const uint32_t*)(Bs + n * AWH + kk + 2 * lt + 8);
                mma_f16(acc[0][nt], aF[0][0], aF[0][1], aF[0][2], aF[0][3], b0, b1);
                mma_f16(acc[1][nt], aF[1][0], aF[1][1], aF[1][2], aF[1][3], b0, b1);
            }
        }
        __syncthreads();
    }
#undef ISSUE

#pragma unroll
    for (int mt = 0; mt < 2; mt++) {
#pragma unroll
        for (int nt = 0; nt < 8; nt++) {
            int r = m0 + wm * 32 + mt * 16 + lg;
            int c = n0 + wn * 64 + nt * 8 + lt * 2;
            float bv0 = bias[c], bv1 = bias[c + 1];
            float2 v01 = make_float2(acc[mt][nt][0] + bv0, acc[mt][nt][1] + bv1);
            *reinterpret_cast<float2*>(C + (size_t)r * N + c) = v01;
            float2 v23 = make_float2(acc[mt][nt][2] + bv0, acc[mt][nt][3] + bv1);
            *reinterpret_cast<float2*>(C + (size_t)(r + 8) * N + c) = v23;
        }
    }
}

// ---------------- persistent GRU recurrence (tf32, unchanged math) -------------
#define RECUR_SMEM (98304 + 24576)

// load one 8-k group of packed A fragments (4x LDG.64, fully coalesced)
__device__ __forceinline__ void ld_frag(const float* cur, int kg, int lg, int lt,
                                        float2 fr[4]) {
    const float* base = cur + kg * 256 + lt * 2;
    fr[0] = ldcg2(base + lg * 8);
    fr[1] = ldcg2(base + (lg + 8) * 8);
    fr[2] = ldcg2(base + (lg + 16) * 8);
    fr[3] = ldcg2(base + (lg + 24) * 8);
}

// phase 0: U=U0, seq=g_h1seq(+g_h1h), s0p=g_hp0A.
// phase 1: U=U1, seq=g_seq(+g_seqh), s0p=g_hp0B.
__global__ __launch_bounds__(256, 1)
void gru_recur(int phase, const float* __restrict__ U,
               const float* __restrict__ bh,      // bias row 1 (b[1])
               const float* __restrict__ hinit,   // [32][1024] row-major (exact)
               float* __restrict__ out)           // d_out (final hidden at t=63)
{
    extern __shared__ float smem[];
    float2* sW = reinterpret_cast<float2*>(smem);        // [3*128*32] float2
    float*  sWf = smem;                                  // scalar view
    float*  Sp = smem + 24576;                           // [8][3][32][8]

    float*  seq  = phase ? g_seq  : g_h1seq;
    __half* seqh = phase ? g_seqh : g_h1h;
    const float* s0p = phase ? g_hp0B : g_hp0A;

    int tid = threadIdx.x, warp = tid >> 5, lane = tid & 31;
    int lg = lane >> 2, lt = lane & 3;
    int j0 = blockIdx.x * 8;

    // one-time weight gather: coalesced reads (4 full sectors / LDG)
    for (int e = tid; e < 3 * 8192; e += 256) {
        int g = e >> 13;
        int r = e & 8191;
        int k = r >> 3;
        int jj = r & 7;
        float w = U[(size_t)k * G3H + g * HH + j0 + jj];
        int wwarp = k >> 7, kk = k & 127, ks = kk >> 3, c = kk & 7;
        int wlt = c & 3, half = c >> 2;
        int wlane = jj * 4 + wlt;
        sWf[(g * 4096 + (wwarp * 16 + ks) * 32 + wlane) * 2 + half] = f2tff(w);
    }
    __syncthreads();

    // epilogue-invariant operands
    int eb = tid >> 3, ejj = tid & 7;
    int ej = j0 + ejj;
    float bhz = bh[ej], bhr = bh[HH + ej], bhh = bh[2 * HH + ej];
    const float* gxrow = g_gx0 + (size_t)(eb * TT) * G3H;

    for (int t = 0; t < TT; t++) {
        const float* cur = (t == 0) ? s0p : g_hp[t & 1];
        float* nxt = g_hp[(t + 1) & 1];

        // prefetch epilogue operands (hidden under the mma loop)
        const float* gxr = gxrow + (size_t)t * G3H;
        float pgx0 = gxr[ej], pgx1 = gxr[HH + ej], pgx2 = gxr[2 * HH + ej];
        float pho = (t == 0) ? hinit[eb * HH + ej]
                             : seq[((size_t)eb * TT + t - 1) * HH + ej];

        float acc[3][2][4];
#pragma unroll
        for (int g = 0; g < 3; g++)
#pragma unroll
            for (int m = 0; m < 2; m++)
#pragma unroll
                for (int q = 0; q < 4; q++) acc[g][m][q] = 0.0f;

        // depth-4 software pipeline over 16 k-groups
        float2 fr[4][4];
        ld_frag(cur, warp * 16 + 0, lg, lt, fr[0]);
        ld_frag(cur, warp * 16 + 1, lg, lt, fr[1]);
        ld_frag(cur, warp * 16 + 2, lg, lt, fr[2]);
#pragma unroll
        for (int ks = 0; ks < 16; ks++) {
            if (ks + 3 < 16) ld_frag(cur, warp * 16 + ks + 3, lg, lt, fr[(ks + 3) & 3]);
            const float2* f = fr[ks & 3];
            uint32_t a00 = __float_as_uint(f[0].x), a01 = __float_as_uint(f[1].x);
            uint32_t a02 = __float_as_uint(f[0].y), a03 = __float_as_uint(f[1].y);
            uint32_t a10 = __float_as_uint(f[2].x), a11 = __float_as_uint(f[3].x);
            uint32_t a12 = __float_as_uint(f[2].y), a13 = __float_as_uint(f[3].y);
#pragma unroll
            for (int g = 0; g < 3; g++) {
                float2 w = sW[g * 4096 + (warp * 16 + ks) * 32 + lane];
                uint32_t b0 = __float_as_uint(w.x), b1 = __float_as_uint(w.y);
                mma_tf32(acc[g][0], a00, a01, a02, a03, b0, b1);
                mma_tf32(acc[g][1], a10, a11, a12, a13, b0, b1);
            }
        }

        // cross-warp K reduction via SMEM
#pragma unroll
        for (int g = 0; g < 3; g++)
#pragma unroll
            for (int mt = 0; mt < 2; mt++) {
                int rr = mt * 16 + lg;
                float* sb = Sp + ((warp * 3 + g) * 32) * 8;
                sb[rr * 8 + lt * 2]           = acc[g][mt][0];
                sb[rr * 8 + lt * 2 + 1]       = acc[g][mt][1];
                sb[(rr + 8) * 8 + lt * 2]     = acc[g][mt][2];
                sb[(rr + 8) * 8 + lt * 2 + 1] = acc[g][mt][3];
            }
        __syncthreads();

        float sz = 0.f, sr = 0.f, sh = 0.f;
#pragma unroll
        for (int w = 0; w < 8; w++) {
            const float* sb = Sp + (w * 3 * 32) * 8;
            sz += sb[(0 * 32 + eb) * 8 + ejj];
            sr += sb[(1 * 32 + eb) * 8 + ejj];
            sh += sb[(2 * 32 + eb) * 8 + ejj];
        }
        float z = sigm(pgx0 + sz + bhz);
        float r = sigm(pgx1 + sr + bhr);
        float hc = tanhf(pgx2 + r * (sh + bhh));
        float v = z * pho + (1.0f - z) * hc;
        seq[((size_t)eb * TT + t) * HH + ej]  = v;               // exact
        seqh[((size_t)eb * TT + t) * HH + ej] = __float2half(v); // GEMM A operand
        nxt[blockIdx.x * 256 + eb * 8 + ((ejj & 3) * 2 + (ejj >> 2))] = f2tff(v);
        if (t == TT - 1)
            out[BTV + (size_t)phase * BB * HH + eb * HH + ej] = v;

        if (t + 1 < TT) grid_bar2();
    }
}

// ---------------- launch -------------------------------------------------------
extern "C" void kernel_launch(void* const* d_in, const int* in_sizes, int n_in,
                              void* d_out, int out_size) {
    (void)in_sizes; (void)n_in; (void)out_size;
    const int*   X   = (const int*)d_in[0];
    const float* h0  = (const float*)d_in[1];
    const float* emb = (const float*)d_in[2];
    const float* W0  = (const float*)d_in[3];
    const float* U0  = (const float*)d_in[4];
    const float* b0  = (const float*)d_in[5];
    const float* W1  = (const float*)d_in[6];
    const float* U1  = (const float*)d_in[7];
    const float* b1  = (const float*)d_in[8];
    const float* Wd  = (const float*)d_in[9];
    const float* bd  = (const float*)d_in[10];
    float* out = (float*)d_out;

    cudaFuncSetAttribute(gru_recur, cudaFuncAttributeMaxDynamicSharedMemorySize,
                         RECUR_SMEM);
    cudaFuncSetAttribute(gemm_f16, cudaFuncAttributeMaxDynamicSharedMemorySize,
                         GEMM_SMEM);

    // [0] detect + dec_in(fp16) + h0 pack (internal grid barrier)
    prep_all<<<NB, 1024>>>(X, h0, emb);

    // [1..3] weight transposes: S[K][N] fp32 -> D[N][K] fp16
    { dim3 g(G3H / 32, KIN / 32); transpose_h<<<g, 256>>>(W0, 0, KIN, G3H); }
    { dim3 g(G3H / 32, HH / 32);  transpose_h<<<g, 256>>>(W1, 1, HH, G3H); }
    { dim3 g(VV / 32, HH / 32);   transpose_h<<<g, 256>>>(Wd, 2, HH, VV); }

    // [4] gx0 = dec_in @ W0 + b0[0]   (M=2048, N=3072, K=1536)
    gemm_f16<<<(NROWS / 128) * (G3H / 256), 512, GEMM_SMEM>>>(
        0, b0, nullptr, NROWS, G3H, KIN);

    // [5] phase A: layer-0 recurrence  <- ncu -s 5
    gru_recur<<<NB, 256, RECUR_SMEM>>>(0, U0, b0 + G3H, h0, out);

    // [6] gx1 = h1_seq @ W1 + b1[0]   (M=2048, N=3072, K=1024)
    gemm_f16<<<(NROWS / 128) * (G3H / 256), 512, GEMM_SMEM>>>(
        2, b1, nullptr, NROWS, G3H, HH);

    // [7] phase B: layer-1 recurrence
    gru_recur<<<NB, 256, RECUR_SMEM>>>(1, U1, b1 + G3H, h0 + BB * HH, out);

    // [8] logits = seqh @ Wdh + bd -> d_out  (M=2048, N=32000, K=1024)
    gemm_f16<<<(NROWS / 128) * (VV / 256), 512, GEMM_SMEM>>>(
        1, bd, out, NROWS, VV, HH);
}

// round 17
// speedup vs baseline: 2.3381x; 1.1319x over previous
#include <cuda_runtime.h>
#include <cuda_fp16.h>
#include <math.h>
#include <stdint.h>

// Problem constants
#define BB 32
#define TT 64
#define HH 1024
#define EE 512
#define VV 32000
#define NROWS (BB * TT)          // 2048
#define KIN  (EE + HH)           // 1536
#define G3H  (3 * HH)            // 3072
#define NB   128                 // persistent blocks (1/SM, co-resident)
static const size_t BTV = (size_t)BB * TT * VV;  // 65,536,000

// ---------------- device scratch (static; no cudaMalloc anywhere) --------------
__device__ __align__(16) __half g_A0h[NROWS * KIN];    // dec_in, fp16
__device__ __align__(16) float  g_gx0[NROWS * G3H];    // x-gates (exact fp32)
__device__ __align__(16) float  g_h1seq[NROWS * HH];   // h1 exact
__device__ __align__(16) float  g_seq[NROWS * HH];     // h2 exact
__device__ __align__(16) __half g_h1h[NROWS * HH];     // h1 fp16 (GEMM A)
__device__ __align__(16) __half g_seqh[NROWS * HH];    // h2 fp16 (GEMM A)
__device__ __align__(16) __half g_hph[2][BB * HH];     // ping-pong packed h (fp16 frag)
__device__ __align__(16) __half g_hp0Ah[BB * HH];      // packed h0[0]
__device__ __align__(16) __half g_hp0Bh[BB * HH];      // packed h0[1]
__device__ __align__(16) __half g_W0h[(size_t)G3H * KIN];  // W0^T fp16 [n][k]
__device__ __align__(16) __half g_W1h[(size_t)G3H * HH];   // W1^T fp16 [n][k]
__device__ __align__(16) __half g_Wdh[(size_t)VV * HH];    // Wd^T fp16 [n][k]
__device__ int      g_flag;                            // int32-detect flag
__device__ unsigned g_cnt;                             // barrier arrival count
__device__ unsigned g_sense;                           // barrier sense

// ---------------- helpers ------------------------------------------------------
__device__ __forceinline__ void mma_f16(float c[4], uint32_t a0, uint32_t a1,
                                        uint32_t a2, uint32_t a3,
                                        uint32_t b0, uint32_t b1) {
    asm volatile(
        "mma.sync.aligned.m16n8k16.row.col.f32.f16.f16.f32 "
        "{%0,%1,%2,%3}, {%4,%5,%6,%7}, {%8,%9}, {%0,%1,%2,%3};\n"
        : "+f"(c[0]), "+f"(c[1]), "+f"(c[2]), "+f"(c[3])
        : "r"(a0), "r"(a1), "r"(a2), "r"(a3), "r"(b0), "r"(b1));
}

__device__ __forceinline__ uint4 ldcg128(const void* p) {
    uint4 v;
    asm volatile("ld.global.cg.v4.b32 {%0,%1,%2,%3}, [%4];"
                 : "=r"(v.x), "=r"(v.y), "=r"(v.z), "=r"(v.w) : "l"(p));
    return v;
}

__device__ __forceinline__ float sigm(float x) { return 1.0f / (1.0f + expf(-x)); }

// packed fp16 fragment index for state value (b, k) — m16n8k16 A layout.
// lane gets {a0..a3} from ONE 16B load at ((kg*2+mt)*32+lane)*8 halves.
__device__ __forceinline__ int packh(int b, int k) {
    return ((((k >> 4) * 2 + (b >> 4)) * 32 + ((b & 7) << 2) + ((k & 7) >> 1)) << 3)
           + (((k >> 3) & 1) << 2) + (((b >> 3) & 1) << 1) + (k & 1);
}

// ---------------- replay-safe sense-reversing grid barrier (NB blocks) ---------
__device__ __forceinline__ void grid_bar2() {
    __syncthreads();
    if (threadIdx.x == 0) {
        unsigned s;
        asm volatile("ld.acquire.gpu.u32 %0, [%1];" : "=r"(s) : "l"(&g_sense));
        __threadfence();                 // publish this block's global stores
        unsigned old = atomicAdd(&g_cnt, 1u);
        if (old == NB - 1u) {
            g_cnt = 0u;
            __threadfence();
            asm volatile("st.release.gpu.u32 [%0], %1;" :: "l"(&g_sense), "r"(s ^ 1u));
        } else {
            unsigned v;
            do {
                asm volatile("ld.acquire.gpu.u32 %0, [%1];" : "=r"(v) : "l"(&g_sense));
            } while (v == s);
        }
    }
    __syncthreads();
}

// ---------------- prep: detect tokens, build dec_in (fp16), pack h0 ------------
__global__ __launch_bounds__(1024, 1)
void prep_all(const int* __restrict__ Xw, const float* __restrict__ h0,
              const float* __restrict__ emb) {
    int gtid = blockIdx.x * 1024 + threadIdx.x;
    const int GT = NB * 1024;

    // detect int64-vs-int32 (odd words all-zero <=> int64)
    if (gtid < 1024 && Xw[2 * gtid + 1] != 0) atomicOr(&g_flag, 1);
    // pack h0 into fp16 mma-fragment order
    if (gtid < BB * HH) {
        int b = gtid >> 10, k = gtid & 1023;
        int d = packh(b, k);
        g_hp0Ah[d] = __float2half(h0[b * HH + k]);
        g_hp0Bh[d] = __float2half(h0[BB * HH + b * HH + k]);
    }
    grid_bar2();

    bool is64 = (g_flag == 0);
    for (int idx = gtid; idx < NROWS * KIN; idx += GT) {
        int n = idx / KIN;
        int k = idx - n * KIN;
        float v;
        if (k < EE) {
            int tok = is64 ? Xw[2 * n] : Xw[n];
            v = emb[(size_t)tok * EE + k];
        } else {
            int b = n >> 6;                          // n = b*T + t
            v = h0[BB * HH + b * HH + (k - EE)];     // context = h0[1][b]
        }
        g_A0h[idx] = __float2half(v);
    }
}

// ---------------- weight transpose: S[K][N] fp32 -> D[N][K] fp16 ---------------
// float4 loads (high MLP), half2 stores (full sectors). 32x32 tiles.
__global__ __launch_bounds__(256)
void transpose_h(const float* __restrict__ S, int sel, int K, int N) {
    __half* D = (sel == 0) ? g_W0h : (sel == 1 ? g_W1h : g_Wdh);
    __shared__ float tile[32][33];
    int n0 = blockIdx.x * 32, k0 = blockIdx.y * 32;
    int tid = threadIdx.x;
    {
        int r = tid >> 3, c4 = (tid & 7) << 2;
        float4 v = *reinterpret_cast<const float4*>(S + (size_t)(k0 + r) * N + n0 + c4);
        tile[r][c4] = v.x; tile[r][c4 + 1] = v.y;
        tile[r][c4 + 2] = v.z; tile[r][c4 + 3] = v.w;
    }
    __syncthreads();
    int q = tid & 15, nl = tid >> 4;
#pragma unroll
    for (int p = 0; p < 2; p++, nl += 16) {
        __half2 h;
        h.x = __float2half(tile[2 * q][nl]);
        h.y = __float2half(tile[2 * q + 1][nl]);
        *reinterpret_cast<__half2*>(D + (size_t)(n0 + nl) * K + k0 + 2 * q) = h;
    }
}

// ---------------- fp16 GEMM: 4-stage cp.async, m16n8k16, fp32 accum ------------
#define STAGES 4
#define AWH 40
#define A_ST (128 * AWH)                 // halves per A stage = 5120
#define B_ST (256 * AWH)                 // halves per B stage = 10240
#define GEMM_SMEM (STAGES * (A_ST + B_ST) * 2)   // 122880 B

__device__ __forceinline__ void cp16(uint32_t dst, const void* src) {
    asm volatile("cp.async.cg.shared.global [%0], [%1], 16;"
                 :: "r"(dst), "l"(src));
}

// sel==0: gx0 = A0h @ W0h.  sel==1: logits = seqh @ Wdh -> Cext.
// sel==2: gx1 = h1h @ W1h.  (A and B resolved IN DEVICE CODE.)
__global__ __launch_bounds__(512, 1)
void gemm_f16(int sel, const float* __restrict__ bias,
              float* __restrict__ Cext, int M, int N, int K) {
    const __half* A  = (sel == 0) ? g_A0h : (sel == 1 ? g_seqh : g_h1h);
    const __half* Bm = (sel == 0) ? g_W0h : (sel == 1 ? g_Wdh  : g_W1h);
    float* C = (sel == 1) ? Cext : g_gx0;

    extern __shared__ __half hsm[];
    __half* Asm = hsm;                               // [STAGES][128][AWH]
    __half* Bsm = hsm + STAGES * A_ST;               // [STAGES][256][AWH]
    uint32_t a_u32 = (uint32_t)__cvta_generic_to_shared(hsm);
    uint32_t b_u32 = a_u32 + STAGES * A_ST * 2;

    int tid = threadIdx.x;
    int warp = tid >> 5, lane = tid & 31;
    int wm = warp >> 2, wn = warp & 3;               // 4x4 warp grid, 32x64/warp
    int lg = lane >> 2, lt = lane & 3;

    int mtiles = M / 128;
    int bm = blockIdx.x % mtiles;                    // M fast-varying: B-tile L2 reuse
    int bn = blockIdx.x / mtiles;
    int m0 = bm * 128, n0 = bn * 256;

    float acc[2][8][4];
#pragma unroll
    for (int a = 0; a < 2; a++)
#pragma unroll
        for (int b = 0; b < 8; b++)
#pragma unroll
            for (int c = 0; c < 4; c++) acc[a][b][c] = 0.0f;

    int arow = tid >> 2, ac8 = (tid & 3) << 3;
    int brow = tid >> 2, bc8 = (tid & 3) << 3;

    int Tn = K / 32;

#define ISSUE(st, kk0)                                                            \
    do {                                                                          \
        cp16(a_u32 + ((st) * A_ST + arow * AWH + ac8) * 2,                        \
             A + (size_t)(m0 + arow) * K + (kk0) + ac8);                          \
        cp16(b_u32 + ((st) * B_ST + brow * AWH + bc8) * 2,                        \
             Bm + (size_t)(n0 + brow) * K + (kk0) + bc8);                         \
        cp16(b_u32 + ((st) * B_ST + (brow + 128) * AWH + bc8) * 2,                \
             Bm + (size_t)(n0 + brow + 128) * K + (kk0) + bc8);                   \
    } while (0)

    ISSUE(0, 0);
    asm volatile("cp.async.commit_group;");
    ISSUE(1, 32);
    asm volatile("cp.async.commit_group;");
    ISSUE(2, 64);
    asm volatile("cp.async.commit_group;");

    for (int tI = 0; tI < Tn; tI++) {
        asm volatile("cp.async.wait_group 2;");
        __syncthreads();
        int st = tI & (STAGES - 1);

        if (tI + STAGES - 1 < Tn) {
            int ns = (tI + STAGES - 1) & (STAGES - 1);
            ISSUE(ns, (tI + STAGES - 1) * 32);
        }
        asm volatile("cp.async.commit_group;");

        const __half* As = Asm + st * A_ST;
        const __half* Bs = Bsm + st * B_ST;
#pragma unroll
        for (int kk = 0; kk < 32; kk += 16) {
            uint32_t aF[2][4];
#pragma unroll
            for (int mt = 0; mt < 2; mt++) {
                int mr = wm * 32 + mt * 16 + lg;
                aF[mt][0] = *(const uint32_t*)(As + mr * AWH + kk + 2 * lt);
                aF[mt][1] = *(const uint32_t*)(As + (mr + 8) * AWH + kk + 2 * lt);
                aF[mt][2] = *(const uint32_t*)(As + mr * AWH + kk + 2 * lt + 8);
                aF[mt][3] = *(const uint32_t*)(As + (mr + 8) * AWH + kk + 2 * lt + 8);
            }
#pragma unroll
            for (int nt = 0; nt < 8; nt++) {
                int n = wn * 64 + nt * 8 + lg;
                uint32_t b0 = *(const uint32_t*)(Bs + n * AWH + kk + 2 * lt);
                uint32_t b1 = *(const uint32_t*)(Bs + n * AWH + kk + 2 * lt + 8);
                mma_f16(acc[0][nt], aF[0][0], aF[0][1], aF[0][2], aF[0][3], b0, b1);
                mma_f16(acc[1][nt], aF[1][0], aF[1][1], aF[1][2], aF[1][3], b0, b1);
            }
        }
        __syncthreads();
    }
#undef ISSUE

#pragma unroll
    for (int mt = 0; mt < 2; mt++) {
#pragma unroll
        for (int nt = 0; nt < 8; nt++) {
            int r = m0 + wm * 32 + mt * 16 + lg;
            int c = n0 + wn * 64 + nt * 8 + lt * 2;
            float bv0 = bias[c], bv1 = bias[c + 1];
            float2 v01 = make_float2(acc[mt][nt][0] + bv0, acc[mt][nt][1] + bv1);
            *reinterpret_cast<float2*>(C + (size_t)r * N + c) = v01;
            float2 v23 = make_float2(acc[mt][nt][2] + bv0, acc[mt][nt][3] + bv1);
            *reinterpret_cast<float2*>(C + (size_t)(r + 8) * N + c) = v23;
        }
    }
}

// ---------------- persistent GRU recurrence (fp16 mma) -------------------------
// SMEM: fragment-packed fp16 weights (49152 B) + reduce scratch Sp (24576 B).
#define RECUR_SMEM (49152 + 24576)

// phase 0: U=U0, seq=g_h1seq(+g_h1h), s0p=g_hp0Ah.
// phase 1: U=U1, seq=g_seq(+g_seqh), s0p=g_hp0Bh.
__global__ __launch_bounds__(256, 1)
void gru_recur(int phase, const float* __restrict__ U,
               const float* __restrict__ bh,      // bias row 1 (b[1])
               const float* __restrict__ hinit,   // [32][1024] row-major (exact)
               float* __restrict__ out)           // d_out (final hidden at t=63)
{
    extern __shared__ float smem[];
    __half* sWh = reinterpret_cast<__half*>(smem);       // [3][64][32][4] halves
    uint2*  sWu2 = reinterpret_cast<uint2*>(smem);       // uint2 view (8B/lane)
    float*  Sp = smem + 12288;                           // [8][3][32][8] floats

    float*  seq  = phase ? g_seq  : g_h1seq;
    __half* seqh = phase ? g_seqh : g_h1h;
    const __half* s0p = phase ? g_hp0Bh : g_hp0Ah;

    int tid = threadIdx.x, warp = tid >> 5, lane = tid & 31;
    int lg = lane >> 2, lt = lane & 3;
    int j0 = blockIdx.x * 8;

    // one-time weight gather -> fragment-packed fp16 smem (coalesced LDGs)
    for (int e = tid; e < 3 * 8192; e += 256) {
        int g = e >> 13;
        int r = e & 8191;
        int k = r >> 3;
        int jj = r & 7;
        __half w = __float2half(U[(size_t)k * G3H + g * HH + j0 + jj]);
        int kg = k >> 4;
        int wlt = (k & 7) >> 1;
        int hid = (((k >> 3) & 1) << 1) | (k & 1);
        sWh[(((g * 64 + kg) * 32) + jj * 4 + wlt) * 4 + hid] = w;
    }
    __syncthreads();

    // epilogue-invariant operands
    int eb = tid >> 3, ejj = tid & 7;
    int ej = j0 + ejj;
    float bhz = bh[ej], bhr = bh[HH + ej], bhh = bh[2 * HH + ej];
    const float* gxrow = g_gx0 + (size_t)(eb * TT) * G3H;
    int epack = packh(eb, ej);           // packed position this thread writes

    for (int t = 0; t < TT; t++) {
        const __half* cur = (t == 0) ? s0p : g_hph[t & 1];
        __half* nxt = g_hph[(t + 1) & 1];

        // prefetch epilogue operands (hidden under the mma loop)
        const float* gxr = gxrow + (size_t)t * G3H;
        float pgx0 = gxr[ej], pgx1 = gxr[HH + ej], pgx2 = gxr[2 * HH + ej];
        float pho = (t == 0) ? hinit[eb * HH + ej]
                             : seq[((size_t)eb * TT + t - 1) * HH + ej];

        float acc[3][2][4];
#pragma unroll
        for (int g = 0; g < 3; g++)
#pragma unroll
            for (int m = 0; m < 2; m++)
#pragma unroll
                for (int q = 0; q < 4; q++) acc[g][m][q] = 0.0f;

        // issue ALL 16 A-fragment loads up front (one L2-latency wave)
        uint4 fa[8][2];
#pragma unroll
        for (int kgl = 0; kgl < 8; kgl++) {
            int kg = warp * 8 + kgl;
            fa[kgl][0] = ldcg128(cur + ((kg * 2 + 0) * 32 + lane) * 8);
            fa[kgl][1] = ldcg128(cur + ((kg * 2 + 1) * 32 + lane) * 8);
        }
#pragma unroll
        for (int kgl = 0; kgl < 8; kgl++) {
            int kg = warp * 8 + kgl;
#pragma unroll
            for (int g = 0; g < 3; g++) {
                uint2 w = sWu2[(g * 64 + kg) * 32 + lane];
                mma_f16(acc[g][0], fa[kgl][0].x, fa[kgl][0].y, fa[kgl][0].z,
                        fa[kgl][0].w, w.x, w.y);
                mma_f16(acc[g][1], fa[kgl][1].x, fa[kgl][1].y, fa[kgl][1].z,
                        fa[kgl][1].w, w.x, w.y);
            }
        }

        // cross-warp K reduction via SMEM (same C-fragment layout as before)
#pragma unroll
        for (int g = 0; g < 3; g++)
#pragma unroll
            for (int mt = 0; mt < 2; mt++) {
                int rr = mt * 16 + lg;
                float* sb = Sp + ((warp * 3 + g) * 32) * 8;
                sb[rr * 8 + lt * 2]           = acc[g][mt][0];
                sb[rr * 8 + lt * 2 + 1]       = acc[g][mt][1];
                sb[(rr + 8) * 8 + lt * 2]     = acc[g][mt][2];
                sb[(rr + 8) * 8 + lt * 2 + 1] = acc[g][mt][3];
            }
        __syncthreads();

        float sz = 0.f, sr = 0.f, sh = 0.f;
#pragma unroll
        for (int w = 0; w < 8; w++) {
            const float* sb = Sp + (w * 3 * 32) * 8;
            sz += sb[(0 * 32 + eb) * 8 + ejj];
            sr += sb[(1 * 32 + eb) * 8 + ejj];
            sh += sb[(2 * 32 + eb) * 8 + ejj];
        }
        float z = sigm(pgx0 + sz + bhz);
        float r = sigm(pgx1 + sr + bhr);
        float hc = tanhf(pgx2 + r * (sh + bhh));
        float v = z * pho + (1.0f - z) * hc;
        __half hv = __float2half(v);
        seq[((size_t)eb * TT + t) * HH + ej]  = v;    // exact
        seqh[((size_t)eb * TT + t) * HH + ej] = hv;   // GEMM A operand
        nxt[epack] = hv;                              // packed next-state
        if (t == TT - 1)
            out[BTV + (size_t)phase * BB * HH + eb * HH + ej] = v;

        if (t + 1 < TT) grid_bar2();
    }
}

// ---------------- launch -------------------------------------------------------
extern "C" void kernel_launch(void* const* d_in, const int* in_sizes, int n_in,
                              void* d_out, int out_size) {
    (void)in_sizes; (void)n_in; (void)out_size;
    const int*   X   = (const int*)d_in[0];
    const float* h0  = (const float*)d_in[1];
    const float* emb = (const float*)d_in[2];
    const float* W0  = (const float*)d_in[3];
    const float* U0  = (const float*)d_in[4];
    const float* b0  = (const float*)d_in[5];
    const float* W1  = (const float*)d_in[6];
    const float* U1  = (const float*)d_in[7];
    const float* b1  = (const float*)d_in[8];
    const float* Wd  = (const float*)d_in[9];
    const float* bd  = (const float*)d_in[10];
    float* out = (float*)d_out;

    cudaFuncSetAttribute(gru_recur, cudaFuncAttributeMaxDynamicSharedMemorySize,
                         RECUR_SMEM);
    cudaFuncSetAttribute(gemm_f16, cudaFuncAttributeMaxDynamicSharedMemorySize,
                         GEMM_SMEM);

    // [0] detect + dec_in(fp16) + h0 pack (internal grid barrier)
    prep_all<<<NB, 1024>>>(X, h0, emb);

    // [1..3] weight transposes: S[K][N] fp32 -> D[N][K] fp16
    { dim3 g(G3H / 32, KIN / 32); transpose_h<<<g, 256>>>(W0, 0, KIN, G3H); }
    { dim3 g(G3H / 32, HH / 32);  transpose_h<<<g, 256>>>(W1, 1, HH, G3H); }
    { dim3 g(VV / 32, HH / 32);   transpose_h<<<g, 256>>>(Wd, 2, HH, VV); }

    // [4] gx0 = dec_in @ W0 + b0[0]   (M=2048, N=3072, K=1536)
    gemm_f16<<<(NROWS / 128) * (G3H / 256), 512, GEMM_SMEM>>>(
        0, b0, nullptr, NROWS, G3H, KIN);

    // [5] phase A: layer-0 recurrence  <- ncu -s 5
    gru_recur<<<NB, 256, RECUR_SMEM>>>(0, U0, b0 + G3H, h0, out);

    // [6] gx1 = h1_seq @ W1 + b1[0]   (M=2048, N=3072, K=1024)
    gemm_f16<<<(NROWS / 128) * (G3H / 256), 512, GEMM_SMEM>>>(
        2, b1, nullptr, NROWS, G3H, HH);

    // [7] phase B: layer-1 recurrence
    gru_recur<<<NB, 256, RECUR_SMEM>>>(1, U1, b1 + G3H, h0 + BB * HH, out);

    // [8] logits = seqh @ Wdh + bd -> d_out  (M=2048, N=32000, K=1024)
    gemm_f16<<<(NROWS / 128) * (VV / 256), 512, GEMM_SMEM>>>(
        1, bd, out, NROWS, VV, HH);
}